// round 12
// baseline (speedup 1.0000x reference)
#include <cuda_runtime.h>
#include <cuda_fp16.h>
#include <math.h>
#include <stdint.h>

// Problem constants
#define B_   2
#define S_   1024
#define D_   1024
#define E_   8
#define KTOP 2
#define FF_  2048
#define T_   (B_ * S_)
#define OUT_MAIN (T_ * D_)
#define OUT_FULL (OUT_MAIN + T_*E_ + T_*KTOP + T_*KTOP)
#define NW   (E_ * FF_ * D_)
#define CONV1_BLOCKS ((NW / 4) / 256)      // 16384 (w1 conversion in prep)
#define CONV2_Z 32                          // 32*16*8 = 4096 blocks (w2 in gemm1)

// GEMM tiling: 128x256 block tile, BK=128 per stage as 2x64 subtiles
#define BM 128
#define BN 256
#define BK 128
// stage: A sub0 16K | A sub1 16K | B sub0 32K | B sub1 32K  = 96K
#define ASUB   16384
#define BB_OFF 32768
#define BSUB   32768
#define STAGE  98304
#define NSTAGE 2
#define SOFF_BUF 1024
#define SMEM_TOTAL (SOFF_BUF + NSTAGE * STAGE)   // 197632

// Device scratch
__device__ int   g_cnt[E_];
__device__ int   g_tok[E_ * T_];
__device__ float g_wt [E_ * T_];
__device__ __half g_w1h[(size_t)NW];
__device__ __half g_w2h[(size_t)NW];
__device__ __half g_xh[(size_t)T_ * D_];
__device__ __half g_hh[(size_t)E_ * T_ * FF_];

// ---------------------------------------------------------------------------
__device__ __forceinline__ uint32_t smem_u32(const void* p) {
    uint32_t a;
    asm("{ .reg .u64 t; cvta.to.shared.u64 t, %1; cvt.u32.u64 %0, t; }"
        : "=r"(a) : "l"(p));
    return a;
}

// swizzled byte offset inside a [rows][64 fp16] subtile (128B rows, 8x16B chunks)
__device__ __forceinline__ uint32_t swz(int r, int c) {
    return (uint32_t)(r * 128 + ((c ^ (r & 7)) << 4));
}

__device__ __forceinline__ void ldsm_x4(uint32_t addr, uint32_t r[4]) {
    asm volatile("ldmatrix.sync.aligned.m8n8.x4.shared.b16 {%0,%1,%2,%3}, [%4];"
                 : "=r"(r[0]), "=r"(r[1]), "=r"(r[2]), "=r"(r[3]) : "r"(addr));
}

__device__ __forceinline__ void mma_fp16(float c[4], const uint32_t a[4],
                                         uint32_t b0, uint32_t b1) {
    asm volatile("mma.sync.aligned.m16n8k16.row.col.f32.f16.f16.f32 "
                 "{%0,%1,%2,%3}, {%4,%5,%6,%7}, {%8,%9}, {%0,%1,%2,%3};"
                 : "+f"(c[0]), "+f"(c[1]), "+f"(c[2]), "+f"(c[3])
                 : "r"(a[0]), "r"(a[1]), "r"(a[2]), "r"(a[3]),
                   "r"(b0), "r"(b1));
}

__device__ __forceinline__ uint32_t packh(float a, float b) {
    __half2 h = __floats2half2_rn(a, b);
    return *reinterpret_cast<uint32_t*>(&h);
}

__device__ __forceinline__ void cp16(uint32_t dst, const void* src, int bytes) {
    asm volatile("cp.async.cg.shared.global [%0], [%1], 16, %2;"
                 :: "r"(dst), "l"(src), "r"(bytes));
}
#define CP_COMMIT() asm volatile("cp.async.commit_group;" ::: "memory")
#define CP_WAIT0()  asm volatile("cp.async.wait_group 0;" ::: "memory")

// ---------------------------------------------------------------------------
__global__ void zero_kernel(float* __restrict__ out, int n) {
    int i = blockIdx.x * blockDim.x + threadIdx.x;
    if (i < n) out[i] = 0.0f;
    if (blockIdx.x == 0 && threadIdx.x < E_) g_cnt[threadIdx.x] = 0;
}

// ---------------------------------------------------------------------------
// prep: blocks [0, T_) router (+ fused x->fp16); blocks [T_, ...) w1 conversion
// ---------------------------------------------------------------------------
__global__ void prep_kernel(const float* __restrict__ x,
                            const float* __restrict__ rw,
                            const float* __restrict__ w1,
                            float* __restrict__ out, int out_size) {
    if (blockIdx.x >= T_) {
        size_t i = ((size_t)(blockIdx.x - T_) * blockDim.x + threadIdx.x) * 4;
        float4 v = *(const float4*)(w1 + i);
        __half* dst = g_w1h + i;
        *(uint32_t*)dst       = packh(v.x, v.y);
        *(uint32_t*)(dst + 2) = packh(v.z, v.w);
        return;
    }

    const int t = blockIdx.x;
    __shared__ float xs[D_];
    __shared__ float logits[E_];

    for (int i = threadIdx.x; i < D_; i += blockDim.x)
        xs[i] = x[(size_t)t * D_ + i];
    __syncthreads();

    {
        int i0 = threadIdx.x * 4;
        *(uint32_t*)(g_xh + (size_t)t * D_ + i0)     = packh(xs[i0],     xs[i0 + 1]);
        *(uint32_t*)(g_xh + (size_t)t * D_ + i0 + 2) = packh(xs[i0 + 2], xs[i0 + 3]);
    }

    const int w = threadIdx.x >> 5;
    const int lane = threadIdx.x & 31;
    float s = 0.0f;
    const float* rwe = rw + (size_t)w * D_;
    for (int k = lane; k < D_; k += 32) s += xs[k] * rwe[k];
    #pragma unroll
    for (int o = 16; o; o >>= 1) s += __shfl_xor_sync(0xffffffffu, s, o);
    if (lane == 0) logits[w] = s;
    __syncthreads();

    if (threadIdx.x == 0) {
        float mx = logits[0];
        #pragma unroll
        for (int e = 1; e < E_; e++) mx = fmaxf(mx, logits[e]);
        float p[E_]; float sum = 0.0f;
        #pragma unroll
        for (int e = 0; e < E_; e++) { p[e] = expf(logits[e] - mx); sum += p[e]; }
        float inv = 1.0f / sum;
        #pragma unroll
        for (int e = 0; e < E_; e++) p[e] *= inv;

        int i0 = 0;
        #pragma unroll
        for (int e = 1; e < E_; e++) if (p[e] > p[i0]) i0 = e;
        int i1 = (i0 == 0) ? 1 : 0;
        #pragma unroll
        for (int e = 0; e < E_; e++) if (e != i0 && p[e] > p[i1]) i1 = e;

        float w0 = p[i0], w1v = p[i1];
        float rinv = 1.0f / (w0 + w1v);
        w0 *= rinv; w1v *= rinv;

        int s0 = atomicAdd(&g_cnt[i0], 1);
        g_tok[i0 * T_ + s0] = t; g_wt[i0 * T_ + s0] = w0;
        int s1 = atomicAdd(&g_cnt[i1], 1);
        g_tok[i1 * T_ + s1] = t; g_wt[i1 * T_ + s1] = w1v;

        if (out_size >= OUT_FULL) {
            float* probs = out + OUT_MAIN;
            float* idxs  = out + OUT_MAIN + T_ * E_;
            float* wts   = out + OUT_MAIN + T_ * E_ + T_ * KTOP;
            #pragma unroll
            for (int e = 0; e < E_; e++) probs[t * E_ + e] = p[e];
            idxs[t * KTOP + 0] = (float)i0;
            idxs[t * KTOP + 1] = (float)i1;
            wts [t * KTOP + 0] = w0;
            wts [t * KTOP + 1] = w1v;
        }
    }
}

// ---------------------------------------------------------------------------
// one 64-col subtile's MMA phase: warp tile 32x64
// ---------------------------------------------------------------------------
__device__ __forceinline__ void mma_sub(uint32_t abase, uint32_t bbase,
                                        int a_r, int a_c, int b_r, int b_c,
                                        float acc[2][8][4]) {
    #pragma unroll
    for (int ks = 0; ks < 4; ks++) {
        uint32_t ah[2][4], bh[4][4];
        #pragma unroll
        for (int mi = 0; mi < 2; mi++)
            ldsm_x4(abase + swz(a_r + mi * 16, ks * 2 + a_c), ah[mi]);
        #pragma unroll
        for (int nj = 0; nj < 4; nj++)
            ldsm_x4(bbase + swz(b_r + nj * 16, ks * 2 + b_c), bh[nj]);
        #pragma unroll
        for (int mi = 0; mi < 2; mi++)
            #pragma unroll
            for (int nj = 0; nj < 4; nj++)
                #pragma unroll
                for (int h = 0; h < 2; h++)
                    mma_fp16(acc[mi][nj*2+h], ah[mi], bh[nj][h*2], bh[nj][h*2+1]);
    }
}

// ---------------------------------------------------------------------------
// GEMM1 (+ fused w2 conversion in extra z-blocks)
// ---------------------------------------------------------------------------
__global__ void __launch_bounds__(512, 1)
expert_gemm1_mma(const float* __restrict__ w2) {
    // w2 conversion path: blockIdx.z in [E_, E_+CONV2_Z)
    if (blockIdx.z >= E_) {
        int id = ((blockIdx.z - E_) * gridDim.y + blockIdx.y) * gridDim.x + blockIdx.x;
        size_t i = (size_t)id * 4096 + threadIdx.x * 8;
        float4 v0 = *(const float4*)(w2 + i);
        float4 v1 = *(const float4*)(w2 + i + 4);
        __half* dst = g_w2h + i;
        *(uint32_t*)dst       = packh(v0.x, v0.y);
        *(uint32_t*)(dst + 2) = packh(v0.z, v0.w);
        *(uint32_t*)(dst + 4) = packh(v1.x, v1.y);
        *(uint32_t*)(dst + 6) = packh(v1.z, v1.w);
        return;
    }

    extern __shared__ char smem[];
    const int e = blockIdx.z;
    const int n_e = g_cnt[e];
    const int row0 = blockIdx.y * BM;
    if (row0 >= n_e) return;
    const int col0 = blockIdx.x * BN;
    const int tid = threadIdx.x, wid = tid >> 5, lane = tid & 31;

    int* toks = (int*)smem;
    if (tid < BM) {
        int r = row0 + tid;
        toks[tid] = (r < n_e) ? g_tok[e * T_ + r] : -1;
    }
    __syncthreads();
    const uint32_t sb = smem_u32(smem);

    // loader: rows tid>>3 and tid>>3 + 64 for A; 4 rows for B; kc = tid&7
    const int kc = tid & 7;
    const __half* asrc[2]; uint32_t aoff[2]; int abytes[2];
    #pragma unroll
    for (int j = 0; j < 2; j++) {
        int row = (tid + j * 512) >> 3;
        int tok = toks[row];
        abytes[j] = (tok >= 0) ? 16 : 0;
        asrc[j] = g_xh + (size_t)(tok < 0 ? 0 : tok) * D_ + kc * 8;
        aoff[j] = swz(row, kc);
    }
    const __half* bsrc[4]; uint32_t boff[4];
    const __half* wbase = g_w1h + (size_t)e * FF_ * D_;
    #pragma unroll
    for (int j = 0; j < 4; j++) {
        int row = (tid + j * 512) >> 3;
        bsrc[j] = wbase + (size_t)(col0 + row) * D_ + kc * 8;
        boff[j] = BB_OFF + swz(row, kc);
    }

    const int warp_m = wid & 3, warp_n = wid >> 2;
    const int a_r = warp_m * 32 + (lane & 15);
    const int a_c = lane >> 4;
    const int b_r = warp_n * 64 + (lane & 7) + ((lane >> 4) & 1) * 8;
    const int b_c = (lane >> 3) & 1;

    float acc[2][8][4] = {};

    const int S = D_ / BK;   // 8
    // prologue: load stage 0
    {
        uint32_t base = sb + SOFF_BUF;
        #pragma unroll
        for (int sub = 0; sub < 2; sub++) {
            #pragma unroll
            for (int j = 0; j < 2; j++)
                cp16(base + sub * ASUB + aoff[j], asrc[j] + sub * 64, abytes[j]);
            #pragma unroll
            for (int j = 0; j < 4; j++)
                cp16(base + sub * BSUB + boff[j], bsrc[j] + sub * 64, 16);
        }
        CP_COMMIT();
    }

    #pragma unroll 1
    for (int s = 0; s < S; s++) {
        CP_WAIT0();
        __syncthreads();
        if (s + 1 < S) {
            uint32_t base = sb + SOFF_BUF + ((s + 1) & 1) * STAGE;
            const int k1 = (s + 1) * BK;
            #pragma unroll
            for (int sub = 0; sub < 2; sub++) {
                #pragma unroll
                for (int j = 0; j < 2; j++)
                    cp16(base + sub * ASUB + aoff[j], asrc[j] + k1 + sub * 64, abytes[j]);
                #pragma unroll
                for (int j = 0; j < 4; j++)
                    cp16(base + sub * BSUB + boff[j], bsrc[j] + k1 + sub * 64, 16);
            }
            CP_COMMIT();
        }
        uint32_t cbase = sb + SOFF_BUF + (s & 1) * STAGE;
        mma_sub(cbase,          cbase + BB_OFF,        a_r, a_c, b_r, b_c, acc);
        mma_sub(cbase + ASUB,   cbase + BB_OFF + BSUB, a_r, a_c, b_r, b_c, acc);
    }

    const int g = lane >> 2, tq = lane & 3;
    #pragma unroll
    for (int mi = 0; mi < 2; mi++) {
        const int rA = row0 + warp_m * 32 + mi * 16 + g;
        const int rB = rA + 8;
        #pragma unroll
        for (int u = 0; u < 8; u++) {
            const int col = col0 + warp_n * 64 + u * 8 + tq * 2;
            if (rA < n_e) {
                float a = acc[mi][u][0], b = acc[mi][u][1];
                a = a / (1.0f + __expf(-a));
                b = b / (1.0f + __expf(-b));
                *(uint32_t*)(g_hh + ((size_t)e * T_ + rA) * FF_ + col) = packh(a, b);
            }
            if (rB < n_e) {
                float a = acc[mi][u][2], b = acc[mi][u][3];
                a = a / (1.0f + __expf(-a));
                b = b / (1.0f + __expf(-b));
                *(uint32_t*)(g_hh + ((size_t)e * T_ + rB) * FF_ + col) = packh(a, b);
            }
        }
    }
}

// ---------------------------------------------------------------------------
__global__ void __launch_bounds__(512, 1)
expert_gemm2_mma(float* __restrict__ out) {
    extern __shared__ char smem[];
    const int e = blockIdx.z;
    const int n_e = g_cnt[e];
    const int row0 = blockIdx.y * BM;
    if (row0 >= n_e) return;
    const int col0 = blockIdx.x * BN;
    const int tid = threadIdx.x, wid = tid >> 5, lane = tid & 31;

    int*   toks = (int*)smem;
    float* wts  = (float*)(smem + 512);
    if (tid < BM) {
        int r = row0 + tid;
        if (r < n_e) { toks[tid] = g_tok[e * T_ + r]; wts[tid] = g_wt[e * T_ + r]; }
        else         { toks[tid] = 0;                 wts[tid] = 0.0f; }
    }
    __syncthreads();
    const uint32_t sb = smem_u32(smem);

    const int kc = tid & 7;
    const __half* asrc[2]; uint32_t aoff[2];
    #pragma unroll
    for (int j = 0; j < 2; j++) {
        int row = (tid + j * 512) >> 3;
        asrc[j] = g_hh + ((size_t)e * T_ + row0 + row) * FF_ + kc * 8;
        aoff[j] = swz(row, kc);
    }
    const __half* bsrc[4]; uint32_t boff[4];
    const __half* wbase = g_w2h + (size_t)e * D_ * FF_;
    #pragma unroll
    for (int j = 0; j < 4; j++) {
        int row = (tid + j * 512) >> 3;
        bsrc[j] = wbase + (size_t)(col0 + row) * FF_ + kc * 8;
        boff[j] = BB_OFF + swz(row, kc);
    }

    const int warp_m = wid & 3, warp_n = wid >> 2;
    const int a_r = warp_m * 32 + (lane & 15);
    const int a_c = lane >> 4;
    const int b_r = warp_n * 64 + (lane & 7) + ((lane >> 4) & 1) * 8;
    const int b_c = (lane >> 3) & 1;

    float acc[2][8][4] = {};

    const int S = FF_ / BK;   // 16
    {
        uint32_t base = sb + SOFF_BUF;
        #pragma unroll
        for (int sub = 0; sub < 2; sub++) {
            #pragma unroll
            for (int j = 0; j < 2; j++)
                cp16(base + sub * ASUB + aoff[j], asrc[j] + sub * 64, 16);
            #pragma unroll
            for (int j = 0; j < 4; j++)
                cp16(base + sub * BSUB + boff[j], bsrc[j] + sub * 64, 16);
        }
        CP_COMMIT();
    }

    #pragma unroll 1
    for (int s = 0; s < S; s++) {
        CP_WAIT0();
        __syncthreads();
        if (s + 1 < S) {
            uint32_t base = sb + SOFF_BUF + ((s + 1) & 1) * STAGE;
            const int k1 = (s + 1) * BK;
            #pragma unroll
            for (int sub = 0; sub < 2; sub++) {
                #pragma unroll
                for (int j = 0; j < 2; j++)
                    cp16(base + sub * ASUB + aoff[j], asrc[j] + k1 + sub * 64, 16);
                #pragma unroll
                for (int j = 0; j < 4; j++)
                    cp16(base + sub * BSUB + boff[j], bsrc[j] + k1 + sub * 64, 16);
            }
            CP_COMMIT();
        }
        uint32_t cbase = sb + SOFF_BUF + (s & 1) * STAGE;
        mma_sub(cbase,          cbase + BB_OFF,        a_r, a_c, b_r, b_c, acc);
        mma_sub(cbase + ASUB,   cbase + BB_OFF + BSUB, a_r, a_c, b_r, b_c, acc);
    }

    const int g = lane >> 2, tq = lane & 3;
    #pragma unroll
    for (int mi = 0; mi < 2; mi++) {
        const int rlA = warp_m * 32 + mi * 16 + g;
        const int rlB = rlA + 8;
        #pragma unroll
        for (int u = 0; u < 8; u++) {
            const int col = col0 + warp_n * 64 + u * 8 + tq * 2;
            if (row0 + rlA < n_e) {
                float w = wts[rlA];
                float* o = out + (size_t)toks[rlA] * D_ + col;
                atomicAdd(o,     w * acc[mi][u][0]);
                atomicAdd(o + 1, w * acc[mi][u][1]);
            }
            if (row0 + rlB < n_e) {
                float w = wts[rlB];
                float* o = out + (size_t)toks[rlB] * D_ + col;
                atomicAdd(o,     w * acc[mi][u][2]);
                atomicAdd(o + 1, w * acc[mi][u][3]);
            }
        }
    }
}

// ---------------------------------------------------------------------------
extern "C" void kernel_launch(void* const* d_in, const int* in_sizes, int n_in,
                              void* d_out, int out_size) {
    const float* x  = (const float*)d_in[0];
    const float* rw = (const float*)d_in[1];
    const float* w1 = (const float*)d_in[2];
    const float* w2 = (const float*)d_in[3];
    float* out = (float*)d_out;

    cudaFuncSetAttribute(expert_gemm1_mma,
                         cudaFuncAttributeMaxDynamicSharedMemorySize, SMEM_TOTAL);
    cudaFuncSetAttribute(expert_gemm2_mma,
                         cudaFuncAttributeMaxDynamicSharedMemorySize, SMEM_TOTAL);

    zero_kernel<<<(out_size + 255) / 256, 256>>>(out, out_size);
    prep_kernel<<<T_ + CONV1_BLOCKS, 256>>>(x, rw, w1, out, out_size);
    expert_gemm1_mma<<<dim3(FF_ / BN, T_ / BM, E_ + CONV2_Z), 512, SMEM_TOTAL>>>(w2);
    expert_gemm2_mma<<<dim3(D_ / BN, T_ / BM, E_), 512, SMEM_TOTAL>>>(out);
}

// round 13
// speedup vs baseline: 1.0730x; 1.0730x over previous
#include <cuda_runtime.h>
#include <cuda_fp16.h>
#include <math.h>
#include <stdint.h>

// Problem constants
#define B_   2
#define S_   1024
#define D_   1024
#define E_   8
#define KTOP 2
#define FF_  2048
#define T_   (B_ * S_)
#define OUT_MAIN (T_ * D_)
#define OUT_FULL (OUT_MAIN + T_*E_ + T_*KTOP + T_*KTOP)
#define NW   (E_ * FF_ * D_)
#define CONV_BLOCKS ((2 * NW / 4) / 256)   // 32768

// GEMM tiling: 128x128 block tile, 256 threads / 8 warps (4 M x 2 N), warp 32x64
#define BM 128
#define BN 128
#define BK 64
// smem stage: A 16K (128x64 fp16) | B 16K (128x64 fp16)
#define AA_OFF 0
#define BB_OFF 16384
#define STAGE  32768
#define NSTAGE 3
#define SOFF_BUF 1024
#define SMEM_TOTAL (SOFF_BUF + NSTAGE * STAGE)   // 99328 (2 CTAs/SM: 198656 <= 227K)

// Device scratch
__device__ int   g_cnt[E_];
__device__ int   g_tok[E_ * T_];
__device__ float g_wt [E_ * T_];
__device__ __half g_w1h[(size_t)NW];
__device__ __half g_w2h[(size_t)NW];
__device__ __half g_xh[(size_t)T_ * D_];
__device__ __half g_hh[(size_t)E_ * T_ * FF_];

// ---------------------------------------------------------------------------
__device__ __forceinline__ uint32_t smem_u32(const void* p) {
    uint32_t a;
    asm("{ .reg .u64 t; cvta.to.shared.u64 t, %1; cvt.u32.u64 %0, t; }"
        : "=r"(a) : "l"(p));
    return a;
}

__device__ __forceinline__ uint32_t swz(int r, int c) {
    return (uint32_t)(r * 128 + ((c ^ (r & 7)) << 4));
}

__device__ __forceinline__ void ldsm_x4(uint32_t addr, uint32_t r[4]) {
    asm volatile("ldmatrix.sync.aligned.m8n8.x4.shared.b16 {%0,%1,%2,%3}, [%4];"
                 : "=r"(r[0]), "=r"(r[1]), "=r"(r[2]), "=r"(r[3]) : "r"(addr));
}

__device__ __forceinline__ void mma_fp16(float c[4], const uint32_t a[4],
                                         uint32_t b0, uint32_t b1) {
    asm volatile("mma.sync.aligned.m16n8k16.row.col.f32.f16.f16.f32 "
                 "{%0,%1,%2,%3}, {%4,%5,%6,%7}, {%8,%9}, {%0,%1,%2,%3};"
                 : "+f"(c[0]), "+f"(c[1]), "+f"(c[2]), "+f"(c[3])
                 : "r"(a[0]), "r"(a[1]), "r"(a[2]), "r"(a[3]),
                   "r"(b0), "r"(b1));
}

__device__ __forceinline__ uint32_t packh(float a, float b) {
    __half2 h = __floats2half2_rn(a, b);
    return *reinterpret_cast<uint32_t*>(&h);
}

__device__ __forceinline__ void cp16(uint32_t dst, const void* src, int bytes) {
    asm volatile("cp.async.cg.shared.global [%0], [%1], 16, %2;"
                 :: "r"(dst), "l"(src), "r"(bytes));
}
#define CP_COMMIT() asm volatile("cp.async.commit_group;" ::: "memory")
#define CP_WAIT(n)  asm volatile("cp.async.wait_group %0;" :: "n"(n) : "memory")

// ---------------------------------------------------------------------------
__global__ void zero_kernel(float* __restrict__ out, int n) {
    int i = blockIdx.x * blockDim.x + threadIdx.x;
    if (i < n) out[i] = 0.0f;
    if (blockIdx.x == 0 && threadIdx.x < E_) g_cnt[threadIdx.x] = 0;
}

// ---------------------------------------------------------------------------
// prep: blocks [0, T_) router (+ fused x->fp16); blocks [T_, ...) w1+w2 conv
// ---------------------------------------------------------------------------
__global__ void prep_kernel(const float* __restrict__ x,
                            const float* __restrict__ rw,
                            const float* __restrict__ w1,
                            const float* __restrict__ w2,
                            float* __restrict__ out, int out_size) {
    if (blockIdx.x >= T_) {
        size_t i = ((size_t)(blockIdx.x - T_) * blockDim.x + threadIdx.x) * 4;
        const float* src;
        __half* dst;
        if (i < (size_t)NW) { src = w1 + i;        dst = g_w1h + i; }
        else                { src = w2 + (i - NW); dst = g_w2h + (i - NW); }
        float4 v = *(const float4*)src;
        *(uint32_t*)dst       = packh(v.x, v.y);
        *(uint32_t*)(dst + 2) = packh(v.z, v.w);
        return;
    }

    const int t = blockIdx.x;
    __shared__ float xs[D_];
    __shared__ float logits[E_];

    for (int i = threadIdx.x; i < D_; i += blockDim.x)
        xs[i] = x[(size_t)t * D_ + i];
    __syncthreads();

    {
        int i0 = threadIdx.x * 4;
        *(uint32_t*)(g_xh + (size_t)t * D_ + i0)     = packh(xs[i0],     xs[i0 + 1]);
        *(uint32_t*)(g_xh + (size_t)t * D_ + i0 + 2) = packh(xs[i0 + 2], xs[i0 + 3]);
    }

    const int w = threadIdx.x >> 5;
    const int lane = threadIdx.x & 31;
    float s = 0.0f;
    const float* rwe = rw + (size_t)w * D_;
    for (int k = lane; k < D_; k += 32) s += xs[k] * rwe[k];
    #pragma unroll
    for (int o = 16; o; o >>= 1) s += __shfl_xor_sync(0xffffffffu, s, o);
    if (lane == 0) logits[w] = s;
    __syncthreads();

    if (threadIdx.x == 0) {
        float mx = logits[0];
        #pragma unroll
        for (int e = 1; e < E_; e++) mx = fmaxf(mx, logits[e]);
        float p[E_]; float sum = 0.0f;
        #pragma unroll
        for (int e = 0; e < E_; e++) { p[e] = expf(logits[e] - mx); sum += p[e]; }
        float inv = 1.0f / sum;
        #pragma unroll
        for (int e = 0; e < E_; e++) p[e] *= inv;

        int i0 = 0;
        #pragma unroll
        for (int e = 1; e < E_; e++) if (p[e] > p[i0]) i0 = e;
        int i1 = (i0 == 0) ? 1 : 0;
        #pragma unroll
        for (int e = 0; e < E_; e++) if (e != i0 && p[e] > p[i1]) i1 = e;

        float w0 = p[i0], w1v = p[i1];
        float rinv = 1.0f / (w0 + w1v);
        w0 *= rinv; w1v *= rinv;

        int s0 = atomicAdd(&g_cnt[i0], 1);
        g_tok[i0 * T_ + s0] = t; g_wt[i0 * T_ + s0] = w0;
        int s1 = atomicAdd(&g_cnt[i1], 1);
        g_tok[i1 * T_ + s1] = t; g_wt[i1 * T_ + s1] = w1v;

        if (out_size >= OUT_FULL) {
            float* probs = out + OUT_MAIN;
            float* idxs  = out + OUT_MAIN + T_ * E_;
            float* wts   = out + OUT_MAIN + T_ * E_ + T_ * KTOP;
            #pragma unroll
            for (int e = 0; e < E_; e++) probs[t * E_ + e] = p[e];
            idxs[t * KTOP + 0] = (float)i0;
            idxs[t * KTOP + 1] = (float)i1;
            wts [t * KTOP + 0] = w0;
            wts [t * KTOP + 1] = w1v;
        }
    }
}

// ---------------------------------------------------------------------------
// one pipeline stage's MMA phase: warp tile 32x64 (mi 0..1, nj 0..3)
// ---------------------------------------------------------------------------
__device__ __forceinline__ void mma_stage(uint32_t base, int a_r, int a_c,
                                          int b_r, int b_c,
                                          float acc[2][8][4]) {
    #pragma unroll
    for (int ks = 0; ks < 4; ks++) {
        uint32_t ah[2][4], bh[4][4];
        #pragma unroll
        for (int mi = 0; mi < 2; mi++)
            ldsm_x4(base + AA_OFF + swz(a_r + mi * 16, ks * 2 + a_c), ah[mi]);
        #pragma unroll
        for (int nj = 0; nj < 4; nj++)
            ldsm_x4(base + BB_OFF + swz(b_r + nj * 16, ks * 2 + b_c), bh[nj]);
        #pragma unroll
        for (int mi = 0; mi < 2; mi++)
            #pragma unroll
            for (int nj = 0; nj < 4; nj++)
                #pragma unroll
                for (int h = 0; h < 2; h++)
                    mma_fp16(acc[mi][nj*2+h], ah[mi], bh[nj][h*2], bh[nj][h*2+1]);
    }
}

// ---------------------------------------------------------------------------
// GEMM1: H[s,n] = silu( X[tok(s),:] . W1[e,n,:] ), H stored fp16
// ---------------------------------------------------------------------------
__global__ void __launch_bounds__(256, 2)
expert_gemm1_mma() {
    extern __shared__ char smem[];
    const int e = blockIdx.z;
    const int n_e = g_cnt[e];
    const int row0 = blockIdx.y * BM;
    if (row0 >= n_e) return;
    const int col0 = blockIdx.x * BN;
    const int tid = threadIdx.x, wid = tid >> 5, lane = tid & 31;

    int* toks = (int*)smem;
    if (tid < BM) {
        int r = row0 + tid;
        toks[tid] = (r < n_e) ? g_tok[e * T_ + r] : -1;
    }
    __syncthreads();
    const uint32_t sb = smem_u32(smem);

    // loader: 8 chunks/thread/stage (A: 4, B: 4); chunk c = tid + j*256
    const int kc = tid & 7;
    const __half* asrc[4]; uint32_t aoff[4]; int abytes[4];
    #pragma unroll
    for (int j = 0; j < 4; j++) {
        int row = (tid + j * 256) >> 3;
        int tok = toks[row];
        abytes[j] = (tok >= 0) ? 16 : 0;
        asrc[j] = g_xh + (size_t)(tok < 0 ? 0 : tok) * D_ + kc * 8;
        aoff[j] = AA_OFF + swz(row, kc);
    }
    const __half* bsrc[4]; uint32_t boff[4];
    const __half* wbase = g_w1h + (size_t)e * FF_ * D_;
    #pragma unroll
    for (int j = 0; j < 4; j++) {
        int row = (tid + j * 256) >> 3;
        bsrc[j] = wbase + (size_t)(col0 + row) * D_ + kc * 8;
        boff[j] = BB_OFF + swz(row, kc);
    }

    // mma role: 4 M x 2 N warp grid, warp tile 32x64
    const int warp_m = wid & 3, warp_n = wid >> 2;
    const int a_r = warp_m * 32 + (lane & 15);
    const int a_c = lane >> 4;
    const int b_r = warp_n * 64 + (lane & 7) + ((lane >> 4) & 1) * 8;
    const int b_c = (lane >> 3) & 1;

    float acc[2][8][4] = {};

    const int S = D_ / BK;   // 16
    #pragma unroll
    for (int ps = 0; ps < 2; ps++) {
        uint32_t base = sb + SOFF_BUF + ps * STAGE;
        #pragma unroll
        for (int j = 0; j < 4; j++) cp16(base + aoff[j], asrc[j] + ps * BK, abytes[j]);
        #pragma unroll
        for (int j = 0; j < 4; j++) cp16(base + boff[j], bsrc[j] + ps * BK, 16);
        CP_COMMIT();
    }

    #pragma unroll 1
    for (int s = 0; s < S; s++) {
        if (s + 1 < S) { CP_WAIT(1); } else { CP_WAIT(0); }
        __syncthreads();
        if (s + 2 < S) {
            uint32_t base = sb + SOFF_BUF + ((s + 2) % NSTAGE) * STAGE;
            #pragma unroll
            for (int j = 0; j < 4; j++) cp16(base + aoff[j], asrc[j] + (s+2) * BK, abytes[j]);
            #pragma unroll
            for (int j = 0; j < 4; j++) cp16(base + boff[j], bsrc[j] + (s+2) * BK, 16);
            CP_COMMIT();
        }
        mma_stage(sb + SOFF_BUF + (s % NSTAGE) * STAGE, a_r, a_c, b_r, b_c, acc);
    }

    // epilogue: silu -> fp16 -> g_hh
    const int g = lane >> 2, tq = lane & 3;
    #pragma unroll
    for (int mi = 0; mi < 2; mi++) {
        const int rA = row0 + warp_m * 32 + mi * 16 + g;
        const int rB = rA + 8;
        #pragma unroll
        for (int u = 0; u < 8; u++) {
            const int col = col0 + warp_n * 64 + u * 8 + tq * 2;
            if (rA < n_e) {
                float a = acc[mi][u][0], b = acc[mi][u][1];
                a = a / (1.0f + __expf(-a));
                b = b / (1.0f + __expf(-b));
                *(uint32_t*)(g_hh + ((size_t)e * T_ + rA) * FF_ + col) = packh(a, b);
            }
            if (rB < n_e) {
                float a = acc[mi][u][2], b = acc[mi][u][3];
                a = a / (1.0f + __expf(-a));
                b = b / (1.0f + __expf(-b));
                *(uint32_t*)(g_hh + ((size_t)e * T_ + rB) * FF_ + col) = packh(a, b);
            }
        }
    }
}

// ---------------------------------------------------------------------------
// GEMM2: out[tok(s),n] += wt(s) * ( H[s,:] . W2[e,n,:] )
// ---------------------------------------------------------------------------
__global__ void __launch_bounds__(256, 2)
expert_gemm2_mma(float* __restrict__ out) {
    extern __shared__ char smem[];
    const int e = blockIdx.z;
    const int n_e = g_cnt[e];
    const int row0 = blockIdx.y * BM;
    if (row0 >= n_e) return;
    const int col0 = blockIdx.x * BN;
    const int tid = threadIdx.x, wid = tid >> 5, lane = tid & 31;

    int*   toks = (int*)smem;
    float* wts  = (float*)(smem + 512);
    if (tid < BM) {
        int r = row0 + tid;
        if (r < n_e) { toks[tid] = g_tok[e * T_ + r]; wts[tid] = g_wt[e * T_ + r]; }
        else         { toks[tid] = 0;                 wts[tid] = 0.0f; }
    }
    __syncthreads();
    const uint32_t sb = smem_u32(smem);

    const int kc = tid & 7;
    const __half* asrc[4]; uint32_t aoff[4];
    #pragma unroll
    for (int j = 0; j < 4; j++) {
        int row = (tid + j * 256) >> 3;
        asrc[j] = g_hh + ((size_t)e * T_ + row0 + row) * FF_ + kc * 8;
        aoff[j] = AA_OFF + swz(row, kc);
    }
    const __half* bsrc[4]; uint32_t boff[4];
    const __half* wbase = g_w2h + (size_t)e * D_ * FF_;
    #pragma unroll
    for (int j = 0; j < 4; j++) {
        int row = (tid + j * 256) >> 3;
        bsrc[j] = wbase + (size_t)(col0 + row) * FF_ + kc * 8;
        boff[j] = BB_OFF + swz(row, kc);
    }

    const int warp_m = wid & 3, warp_n = wid >> 2;
    const int a_r = warp_m * 32 + (lane & 15);
    const int a_c = lane >> 4;
    const int b_r = warp_n * 64 + (lane & 7) + ((lane >> 4) & 1) * 8;
    const int b_c = (lane >> 3) & 1;

    float acc[2][8][4] = {};

    const int S = FF_ / BK;   // 32
    #pragma unroll
    for (int ps = 0; ps < 2; ps++) {
        uint32_t base = sb + SOFF_BUF + ps * STAGE;
        #pragma unroll
        for (int j = 0; j < 4; j++) cp16(base + aoff[j], asrc[j] + ps * BK, 16);
        #pragma unroll
        for (int j = 0; j < 4; j++) cp16(base + boff[j], bsrc[j] + ps * BK, 16);
        CP_COMMIT();
    }

    #pragma unroll 1
    for (int s = 0; s < S; s++) {
        if (s + 1 < S) { CP_WAIT(1); } else { CP_WAIT(0); }
        __syncthreads();
        if (s + 2 < S) {
            uint32_t base = sb + SOFF_BUF + ((s + 2) % NSTAGE) * STAGE;
            #pragma unroll
            for (int j = 0; j < 4; j++) cp16(base + aoff[j], asrc[j] + (s+2) * BK, 16);
            #pragma unroll
            for (int j = 0; j < 4; j++) cp16(base + boff[j], bsrc[j] + (s+2) * BK, 16);
            CP_COMMIT();
        }
        mma_stage(sb + SOFF_BUF + (s % NSTAGE) * STAGE, a_r, a_c, b_r, b_c, acc);
    }

    const int g = lane >> 2, tq = lane & 3;
    #pragma unroll
    for (int mi = 0; mi < 2; mi++) {
        const int rlA = warp_m * 32 + mi * 16 + g;
        const int rlB = rlA + 8;
        #pragma unroll
        for (int u = 0; u < 8; u++) {
            const int col = col0 + warp_n * 64 + u * 8 + tq * 2;
            if (row0 + rlA < n_e) {
                float w = wts[rlA];
                float* o = out + (size_t)toks[rlA] * D_ + col;
                atomicAdd(o,     w * acc[mi][u][0]);
                atomicAdd(o + 1, w * acc[mi][u][1]);
            }
            if (row0 + rlB < n_e) {
                float w = wts[rlB];
                float* o = out + (size_t)toks[rlB] * D_ + col;
                atomicAdd(o,     w * acc[mi][u][2]);
                atomicAdd(o + 1, w * acc[mi][u][3]);
            }
        }
    }
}

// ---------------------------------------------------------------------------
extern "C" void kernel_launch(void* const* d_in, const int* in_sizes, int n_in,
                              void* d_out, int out_size) {
    const float* x  = (const float*)d_in[0];
    const float* rw = (const float*)d_in[1];
    const float* w1 = (const float*)d_in[2];
    const float* w2 = (const float*)d_in[3];
    float* out = (float*)d_out;

    cudaFuncSetAttribute(expert_gemm1_mma,
                         cudaFuncAttributeMaxDynamicSharedMemorySize, SMEM_TOTAL);
    cudaFuncSetAttribute(expert_gemm2_mma,
                         cudaFuncAttributeMaxDynamicSharedMemorySize, SMEM_TOTAL);

    zero_kernel<<<(out_size + 255) / 256, 256>>>(out, out_size);
    prep_kernel<<<T_ + CONV_BLOCKS, 256>>>(x, rw, w1, w2, out, out_size);
    expert_gemm1_mma<<<dim3(FF_ / BN, T_ / BM, E_), 256, SMEM_TOTAL>>>();
    expert_gemm2_mma<<<dim3(D_ / BN, T_ / BM, E_), 256, SMEM_TOTAL>>>(out);
}